// round 10
// baseline (speedup 1.0000x reference)
#include <cuda_runtime.h>
#include <cuda_bf16.h>
#include <math.h>

#define N_NODES 50000
#define DEG     16
#define BATCH   32
#define FEAT    5
#define NDRV    500
#define N_MID   5
#define FMAX    (NDRV * DEG)   // worst-case frontier size (8000)

typedef unsigned long long ull;

// ---------------------------------------------------------------------------
// f32x2 packed helpers (sm_103a packed fp32 pipe; 2 IEEE fp32 FMAs per issue,
// bit-identical to scalar fmaf -> no accuracy change).
// ---------------------------------------------------------------------------
__device__ __forceinline__ ull packf2(float lo, float hi) {
    ull r; asm("mov.b64 %0, {%1, %2};" : "=l"(r) : "f"(lo), "f"(hi)); return r;
}
__device__ __forceinline__ void unpackf2(ull v, float& lo, float& hi) {
    asm("mov.b64 {%0, %1}, %2;" : "=f"(lo), "=f"(hi) : "l"(v));
}
__device__ __forceinline__ void fma2(ull& acc, ull a, ull b) {
    asm("fma.rn.f32x2 %0, %1, %2, %0;" : "+l"(acc) : "l"(a), "l"(b));
}

// Ping-pong node-state buffers, [N, B] node-major: each neighbor gather is one
// coalesced 128B line per (node, d).
__device__ float g_zbuf0[N_NODES * BATCH];
__device__ float g_zbuf1[N_NODES * BATCH];

// Frontier (neighbors of drivers) for the sparse pass 3.
__device__ int g_mark[N_NODES];
__device__ int g_frontier[FMAX];
__device__ int g_fcount;

// Duplicated ({w,w}) parameters, produced by pack_params each launch.
__device__ ull g_wp_first[FEAT * 3];
__device__ ull g_wp_mid[N_MID * FEAT * FEAT * 3];
__device__ ull g_wp_last[FEAT * 3];
__device__ ull g_bp_first[FEAT];
__device__ ull g_bp_mid[N_MID * FEAT];
__device__ ull g_bp_last[1];

__device__ __forceinline__ ull dup_bits(float v) {
    unsigned u = __float_as_uint(v);
    return ((ull)u << 32) | (ull)u;
}

#define WM_SZ (N_MID * FEAT * FEAT * 3)   // 375, the largest table

__global__ void pack_params(const float* __restrict__ wf, const float* __restrict__ bf,
                            const float* __restrict__ wm, const float* __restrict__ bm,
                            const float* __restrict__ wl, const float* __restrict__ bl) {
    for (int i = blockIdx.x * blockDim.x + threadIdx.x; i < WM_SZ;
         i += gridDim.x * blockDim.x) {
        g_wp_mid[i] = dup_bits(wm[i]);
        if (i < FEAT * 3)     g_wp_first[i] = dup_bits(wf[i]);
        if (i < FEAT * 3)     g_wp_last[i]  = dup_bits(wl[i]);
        if (i < FEAT)         g_bp_first[i] = dup_bits(bf[i]);
        if (i < N_MID * FEAT) g_bp_mid[i]   = dup_bits(bm[i]);
        if (i == 0)           g_bp_last[0]  = dup_bits(bl[0]);
    }
}

// ---------------------------------------------------------------------------
// Prep: zero the [B, N] output (harness poisons d_out to 0xAA), clear the
// frontier marks, reset the frontier counter. One kernel, disjoint buffers.
// ---------------------------------------------------------------------------
#define OUT_QUADS (N_NODES * BATCH / 4)   // 400000 float4s

__global__ void prep_kernel(float4* __restrict__ out) {
    int i = blockIdx.x * blockDim.x + threadIdx.x;
    if (i < OUT_QUADS) out[i] = make_float4(0.f, 0.f, 0.f, 0.f);
    if (i < N_NODES)   g_mark[i] = 0;
    if (i == 0)        g_fcount = 0;
}

// ---------------------------------------------------------------------------
// Frontier construction: insert each unique neighbor of a driver node exactly
// once (atomicExch dedup). List ORDER is nondeterministic but the SET is
// deterministic, and every frontier node writes only its own output slot ->
// the final output is bitwise deterministic.
// ---------------------------------------------------------------------------
__global__ void build_frontier_kernel(const int* __restrict__ drivers,
                                      const int* __restrict__ nbr) {
    int i = blockIdx.x * blockDim.x + threadIdx.x;   // over NDRV*DEG edges
    if (i < NDRV * DEG) {
        int d = drivers[i / DEG];
        int nb = nbr[d * DEG + (i % DEG)];
        if (atomicExch(&g_mark[nb], 1) == 0) {
            int pos = atomicAdd(&g_fcount, 1);
            g_frontier[pos] = nb;
        }
    }
}

// ---------------------------------------------------------------------------
// Tiled transpose x [B, N] -> g_zbuf0 [N, B]. 32x32 smem tile (padded stride
// 33): reads AND writes fully coalesced.
// ---------------------------------------------------------------------------
__global__ void transpose_kernel(const float* __restrict__ x) {
    __shared__ float tile[32][33];
    int n0 = blockIdx.x * 32;
    int tx = threadIdx.x;                  // 0..31
    int ty = threadIdx.y;                  // 0..7
#pragma unroll
    for (int r = 0; r < 32; r += 8) {
        int n = n0 + tx;
        if (n < N_NODES) tile[ty + r][tx] = x[(ty + r) * N_NODES + n];
    }
    __syncthreads();
#pragma unroll
    for (int r = 0; r < 32; r += 8) {
        int n = n0 + ty + r;
        if (n < N_NODES) g_zbuf0[n * BATCH + tx] = tile[tx][ty + r];
    }
}

// ---------------------------------------------------------------------------
// Packed conv: CIN->FEAT channels, width WIN -> WIN-2 (k=3, VALID), ReLU.
// I/O packed as pairs {v[2k], v[2k+1]}; only tap-1 needs a cross-pair repack,
// hoisted out of the co-loop (built once per ci, reused by all 5 channels).
// ---------------------------------------------------------------------------
template <int CIN, int WIN>
__device__ __forceinline__ void convp(const ull* __restrict__ in,
                                      ull* __restrict__ out,
                                      const ull* __restrict__ w2,
                                      const ull* __restrict__ b2) {
    constexpr int WOUT  = WIN - 2;
    constexpr int NPIN  = WIN / 2;
    constexpr int NPOUT = WOUT / 2;

    ull acc[FEAT * NPOUT];
#pragma unroll
    for (int co = 0; co < FEAT; co++) {
        ull bb = b2[co];
#pragma unroll
        for (int k = 0; k < NPOUT; k++) acc[co * NPOUT + k] = bb;
    }

#pragma unroll
    for (int ci = 0; ci < CIN; ci++) {
        ull o[NPOUT];
#pragma unroll
        for (int k = 0; k < NPOUT; k++) {
            float a0, a1, b0, b1;
            unpackf2(in[ci * NPIN + k],     a0, a1);
            unpackf2(in[ci * NPIN + k + 1], b0, b1);
            o[k] = packf2(a1, b0);               // {v[2k+1], v[2k+2]}
        }
#pragma unroll
        for (int co = 0; co < FEAT; co++) {
            const ull w0 = w2[(co * CIN + ci) * 3 + 0];
            const ull w1 = w2[(co * CIN + ci) * 3 + 1];
            const ull wv = w2[(co * CIN + ci) * 3 + 2];
#pragma unroll
            for (int k = 0; k < NPOUT; k++) {
                fma2(acc[co * NPOUT + k], w0, in[ci * NPIN + k]);
                fma2(acc[co * NPOUT + k], w1, o[k]);
                fma2(acc[co * NPOUT + k], wv, in[ci * NPIN + k + 1]);
            }
        }
    }

#pragma unroll
    for (int co = 0; co < FEAT; co++)
#pragma unroll
        for (int k = 0; k < NPOUT; k++) {
            float lo, hi;
            unpackf2(acc[co * NPOUT + k], lo, hi);
            out[co * NPOUT + k] = packf2(fmaxf(lo, 0.0f), fmaxf(hi, 0.0f));
        }
}

// ---------------------------------------------------------------------------
// Shared weight staging + the per-(node,lane) pass body, common to all pass
// kernel variants so the hot code is identical.
// ---------------------------------------------------------------------------
struct SWeights {
    ull wf[FEAT * 3];
    ull wm[WM_SZ];
    ull wl[FEAT * 3];
    ull bf[FEAT];
    ull bm[N_MID * FEAT];
    ull bl[1];
};

__device__ __forceinline__ void load_weights(SWeights* s, int t) {
    for (int i = t; i < FEAT * 3; i += 128)     s->wf[i] = g_wp_first[i];
    for (int i = t; i < WM_SZ; i += 128)        s->wm[i] = g_wp_mid[i];
    for (int i = t; i < FEAT * 3; i += 128)     s->wl[i] = g_wp_last[i];
    for (int i = t; i < FEAT; i += 128)         s->bf[i] = g_bp_first[i];
    for (int i = t; i < N_MID * FEAT; i += 128) s->bm[i] = g_bp_mid[i];
    if (t == 0)                                 s->bl[0] = g_bp_last[0];
    __syncthreads();
}

__device__ __forceinline__ void node_pass(int n, int lane,
                                          const float* __restrict__ zin,
                                          float* __restrict__ zout,
                                          const SWeights* __restrict__ s,
                                          const int* __restrict__ nbr) {
    // Gather 16 neighbor states (warp-uniform index row, coalesced state rows).
    ull gp[DEG / 2];
    const int4* nb4 = reinterpret_cast<const int4*>(nbr + n * DEG);
#pragma unroll
    for (int q = 0; q < 4; q++) {
        int4 v = __ldg(nb4 + q);
        float z0 = zin[v.x * BATCH + lane];
        float z1 = zin[v.y * BATCH + lane];
        float z2 = zin[v.z * BATCH + lane];
        float z3 = zin[v.w * BATCH + lane];
        gp[q * 2 + 0] = packf2(z0, z1);
        gp[q * 2 + 1] = packf2(z2, z3);
    }

    ull a[FEAT * 7];
    ull c[FEAT * 6];
    convp<1, 16>(gp, a, s->wf, s->bf);                        // a: 5 x w14
    convp<FEAT, 14>(a, c, s->wm + 0 * 75, s->bm + 0 * FEAT);  // c: 5 x w12
    convp<FEAT, 12>(c, a, s->wm + 1 * 75, s->bm + 1 * FEAT);  // a: 5 x w10
    convp<FEAT, 10>(a, c, s->wm + 2 * 75, s->bm + 2 * FEAT);  // c: 5 x w8
    convp<FEAT, 8 >(c, a, s->wm + 3 * 75, s->bm + 3 * FEAT);  // a: 5 x w6
    convp<FEAT, 6 >(a, c, s->wm + 4 * 75, s->bm + 4 * FEAT);  // c: 5 x w4

    // Last conv: 5 -> 1, width 4 -> 2 packed {o0, o1}, then avgpool -> 1.
    ull accp = s->bl[0];
#pragma unroll
    for (int ci = 0; ci < FEAT; ci++) {
        ull p0 = c[ci * 2 + 0], p1 = c[ci * 2 + 1];
        float v0, v1, v2, v3;
        unpackf2(p0, v0, v1);
        unpackf2(p1, v2, v3);
        ull om = packf2(v1, v2);
        fma2(accp, s->wl[ci * 3 + 0], p0);
        fma2(accp, s->wl[ci * 3 + 1], om);
        fma2(accp, s->wl[ci * 3 + 2], p1);
    }
    float o0, o1;
    unpackf2(accp, o0, o1);
    o0 = fmaxf(o0, 0.0f);
    o1 = fmaxf(o1, 0.0f);

    zout[n * BATCH + lane] = 0.5f * (o0 + o1);
}

// ---------------------------------------------------------------------------
// Pass variants. Warp = one node across 32 batches (lane = batch).
// __launch_bounds__(128, 2): 256-reg cap guarantees a spill-free body.
// ---------------------------------------------------------------------------
__global__ __launch_bounds__(128, 2) void pass_full_kernel(int flip,
                                                           const int* __restrict__ nbr) {
    const float* zin  = flip ? g_zbuf1 : g_zbuf0;
    float*       zout = flip ? g_zbuf0 : g_zbuf1;
    __shared__ SWeights s;
    int t = threadIdx.x;
    load_weights(&s, t);

    int n = (blockIdx.x * blockDim.x + t) >> 5;
    if (n >= N_NODES) return;
    node_pass(n, t & 31, zin, zout, &s, nbr);
}

// Pass 3: only nodes in the frontier (neighbors of drivers). z0 -> z1.
__global__ __launch_bounds__(128, 2) void pass_frontier_kernel(const int* __restrict__ nbr) {
    __shared__ SWeights s;
    int t = threadIdx.x;
    load_weights(&s, t);

    int w = (blockIdx.x * blockDim.x + t) >> 5;
    if (w >= g_fcount) return;
    node_pass(g_frontier[w], t & 31, g_zbuf0, g_zbuf1, &s, nbr);
}

// Pass 4: only the driver nodes themselves. z1 -> z0.
__global__ __launch_bounds__(128, 2) void pass_driver_kernel(const int* __restrict__ nbr,
                                                             const int* __restrict__ drivers) {
    __shared__ SWeights s;
    int t = threadIdx.x;
    load_weights(&s, t);

    int w = (blockIdx.x * blockDim.x + t) >> 5;
    if (w >= NDRV) return;
    node_pass(drivers[w], t & 31, g_zbuf1, g_zbuf0, &s, nbr);
}

// ---------------------------------------------------------------------------
// Final softmax over [500 driver values union N-500 exact zeros]; output is
// nonzero only at driver columns (one-hot driver_matrix handled analytically):
//   denom = sum_drv exp(v-m) + (N-NDRV)*exp(-m),  m = max(0, max_drv v).
// One block per batch. Driver values live in g_zbuf0 after pass 4.
// ---------------------------------------------------------------------------
__global__ void softmax_kernel(const int* __restrict__ drivers,
                               float* __restrict__ out) {
    const float* __restrict__ zt = g_zbuf0;
    int b = blockIdx.x;
    int t = threadIdx.x;
    __shared__ float sred[256];

    float lm = 0.0f;  // implicit zeros of the non-driver entries
    for (int j = t; j < NDRV; j += 256)
        lm = fmaxf(lm, zt[drivers[j] * BATCH + b]);
    sred[t] = lm;
    __syncthreads();
    for (int s = 128; s > 0; s >>= 1) {
        if (t < s) sred[t] = fmaxf(sred[t], sred[t + s]);
        __syncthreads();
    }
    float m = sred[0];
    __syncthreads();

    float ls = 0.0f;
    for (int j = t; j < NDRV; j += 256)
        ls += expf(zt[drivers[j] * BATCH + b] - m);
    sred[t] = ls;
    __syncthreads();
    for (int s = 128; s > 0; s >>= 1) {
        if (t < s) sred[t] += sred[t + s];
        __syncthreads();
    }
    float denom = sred[0] + (float)(N_NODES - NDRV) * expf(-m);
    float inv = 1.0f / denom;

    for (int j = t; j < NDRV; j += 256) {
        int n = drivers[j];
        out[b * N_NODES + n] = expf(zt[n * BATCH + b] - m) * inv;
    }
}

// ---------------------------------------------------------------------------
extern "C" void kernel_launch(void* const* d_in, const int* in_sizes, int n_in,
                              void* d_out, int out_size) {
    const float* x       = (const float*)d_in[0];
    const int*   nbr     = (const int*)  d_in[1];
    const int*   drivers = (const int*)  d_in[2];
    // d_in[3] = driver_matrix (one-hot; handled analytically)
    const float* wf = (const float*)d_in[4];
    const float* bf = (const float*)d_in[5];
    const float* wm = (const float*)d_in[6];
    const float* bm = (const float*)d_in[7];
    const float* wl = (const float*)d_in[8];
    const float* bl = (const float*)d_in[9];
    float* out = (float*)d_out;

    pack_params<<<2, 256>>>(wf, bf, wm, bm, wl, bl);
    prep_kernel<<<(OUT_QUADS + 255) / 256, 256>>>((float4*)out);
    {
        dim3 tb(32, 8);
        transpose_kernel<<<(N_NODES + 31) / 32, tb>>>(x);
    }
    build_frontier_kernel<<<(NDRV * DEG + 255) / 256, 256>>>(drivers, nbr);

    const int FULL_BLOCKS = (N_NODES * 32 + 127) / 128;      // one warp per node
    const int FRONT_BLOCKS = (FMAX * 32 + 127) / 128;        // worst-case frontier
    const int DRV_BLOCKS = (NDRV * 32 + 127) / 128;

    pass_full_kernel<<<FULL_BLOCKS, 128>>>(0, nbr);          // z0 -> z1 (all nodes)
    pass_full_kernel<<<FULL_BLOCKS, 128>>>(1, nbr);          // z1 -> z0 (all nodes)
    pass_frontier_kernel<<<FRONT_BLOCKS, 128>>>(nbr);        // z0 -> z1 (nbrs of drivers)
    pass_driver_kernel<<<DRV_BLOCKS, 128>>>(nbr, drivers);   // z1 -> z0 (drivers only)

    softmax_kernel<<<BATCH, 256>>>(drivers, out);
}

// round 17
// speedup vs baseline: 1.2720x; 1.2720x over previous
#include <cuda_runtime.h>
#include <cuda_bf16.h>
#include <math.h>

#define N_NODES 50000
#define DEG     16
#define BATCH   32
#define FEAT    5
#define NDRV    500
#define N_MID   5
#define FMAX    (NDRV * DEG)   // worst-case frontier size (8000)

typedef unsigned long long ull;

// ---------------------------------------------------------------------------
// f32x2 packed helpers (sm_103a packed fp32 pipe; 2 IEEE fp32 FMAs per issue,
// bit-identical to scalar fmaf -> no accuracy change).
// ---------------------------------------------------------------------------
__device__ __forceinline__ ull packf2(float lo, float hi) {
    ull r; asm("mov.b64 %0, {%1, %2};" : "=l"(r) : "f"(lo), "f"(hi)); return r;
}
__device__ __forceinline__ void unpackf2(ull v, float& lo, float& hi) {
    asm("mov.b64 {%0, %1}, %2;" : "=f"(lo), "=f"(hi) : "l"(v));
}
__device__ __forceinline__ void fma2(ull& acc, ull a, ull b) {
    asm("fma.rn.f32x2 %0, %1, %2, %0;" : "+l"(acc) : "l"(a), "l"(b));
}

// Ping-pong node-state buffers, [N, B] node-major: each neighbor gather is one
// coalesced 128B line per (node, d).
__device__ float g_zbuf0[N_NODES * BATCH];
__device__ float g_zbuf1[N_NODES * BATCH];

// Frontier (neighbors of drivers) for the sparse pass 3.
__device__ int g_mark[N_NODES];
__device__ int g_frontier[FMAX];
__device__ int g_fcount;

// ---------------------------------------------------------------------------
// Parameters: duplicated ({w,w}) pairs packed by pack_params into a staging
// global, then copied into __constant__ so the pass kernels read weights via
// the uniform-const path (LDCU -> UR), relieving GPR even/odd bank pressure
// on the FFMA2 stream (rt 3 -> rt 2 if the UR operand form is used).
// Layout: [wf 15 | wm 375 | wl 15 | bf 5 | bm 25 | bl 1] = 436 ull.
// ---------------------------------------------------------------------------
#define OFF_WF 0
#define OFF_WM 15
#define OFF_WL 390
#define OFF_BF 405
#define OFF_BM 410
#define OFF_BL 435
#define NPARAM 436

__device__   ull g_params[NPARAM];
__constant__ ull c_params[NPARAM];

__device__ __forceinline__ ull dup_bits(float v) {
    unsigned u = __float_as_uint(v);
    return ((ull)u << 32) | (ull)u;
}

__global__ void pack_params(const float* __restrict__ wf, const float* __restrict__ bf,
                            const float* __restrict__ wm, const float* __restrict__ bm,
                            const float* __restrict__ wl, const float* __restrict__ bl) {
    int i = blockIdx.x * blockDim.x + threadIdx.x;
    if (i < 375) g_params[OFF_WM + i] = dup_bits(wm[i]);
    if (i < 15)  g_params[OFF_WF + i] = dup_bits(wf[i]);
    if (i < 15)  g_params[OFF_WL + i] = dup_bits(wl[i]);
    if (i < 5)   g_params[OFF_BF + i] = dup_bits(bf[i]);
    if (i < 25)  g_params[OFF_BM + i] = dup_bits(bm[i]);
    if (i == 0)  g_params[OFF_BL]     = dup_bits(bl[0]);
}

// ---------------------------------------------------------------------------
// Transpose x [B, N] -> g_zbuf0 [N, B] (32x33 padded smem tile, both sides
// coalesced) FUSED with output-zeroing + frontier-mark clearing (disjoint
// buffers; 1563 blocks x 256 threads = 400128 threads covers all of them).
// Fusing keeps pass_full_kernel at kernel-launch index 3 for ncu's fixed
// capture slot regardless of whether the memcpy node counts as a launch.
// ---------------------------------------------------------------------------
#define OUT_QUADS (N_NODES * BATCH / 4)   // 400000 float4s

__global__ void transpose_prep_kernel(const float* __restrict__ x,
                                      float4* __restrict__ out) {
    __shared__ float tile[32][33];
    int tx = threadIdx.x;                  // 0..31
    int ty = threadIdx.y;                  // 0..7
    int t  = ty * 32 + tx;                 // 0..255
    int gid = blockIdx.x * 256 + t;

    // Prep work (independent of the transpose below).
    if (gid < OUT_QUADS) out[gid] = make_float4(0.f, 0.f, 0.f, 0.f);
    if (gid < N_NODES)   g_mark[gid] = 0;
    if (gid == 0)        g_fcount = 0;

    // Tiled transpose of one 32-node stripe.
    int n0 = blockIdx.x * 32;
#pragma unroll
    for (int r = 0; r < 32; r += 8) {
        int n = n0 + tx;
        if (n < N_NODES) tile[ty + r][tx] = x[(ty + r) * N_NODES + n];
    }
    __syncthreads();
#pragma unroll
    for (int r = 0; r < 32; r += 8) {
        int n = n0 + ty + r;
        if (n < N_NODES) g_zbuf0[n * BATCH + tx] = tile[tx][ty + r];
    }
}

// ---------------------------------------------------------------------------
// Frontier construction (after the full passes; only feeds pass_frontier).
// Order nondeterministic, set deterministic; each frontier node writes only
// its own slot -> output bitwise deterministic.
// ---------------------------------------------------------------------------
__global__ void build_frontier_kernel(const int* __restrict__ drivers,
                                      const int* __restrict__ nbr) {
    int i = blockIdx.x * blockDim.x + threadIdx.x;   // over NDRV*DEG edges
    if (i < NDRV * DEG) {
        int d = drivers[i / DEG];
        int nb = nbr[d * DEG + (i % DEG)];
        if (atomicExch(&g_mark[nb], 1) == 0) {
            int pos = atomicAdd(&g_fcount, 1);
            g_frontier[pos] = nb;
        }
    }
}

// ---------------------------------------------------------------------------
// Packed conv: CIN->FEAT channels, width WIN -> WIN-2 (k=3, VALID), ReLU.
// Weights/biases read straight from __constant__ (compile-time offsets via
// template args -> direct const-space addressing, uniform across the warp).
// ---------------------------------------------------------------------------
template <int CIN, int WIN, int WOFF, int BOFF>
__device__ __forceinline__ void convp(const ull* __restrict__ in,
                                      ull* __restrict__ out) {
    constexpr int WOUT  = WIN - 2;
    constexpr int NPIN  = WIN / 2;
    constexpr int NPOUT = WOUT / 2;

    ull acc[FEAT * NPOUT];
#pragma unroll
    for (int co = 0; co < FEAT; co++) {
        ull bb = c_params[BOFF + co];
#pragma unroll
        for (int k = 0; k < NPOUT; k++) acc[co * NPOUT + k] = bb;
    }

#pragma unroll
    for (int ci = 0; ci < CIN; ci++) {
        ull o[NPOUT];
#pragma unroll
        for (int k = 0; k < NPOUT; k++) {
            float a0, a1, b0, b1;
            unpackf2(in[ci * NPIN + k],     a0, a1);
            unpackf2(in[ci * NPIN + k + 1], b0, b1);
            o[k] = packf2(a1, b0);               // {v[2k+1], v[2k+2]}
        }
#pragma unroll
        for (int co = 0; co < FEAT; co++) {
            const ull w0 = c_params[WOFF + (co * CIN + ci) * 3 + 0];
            const ull w1 = c_params[WOFF + (co * CIN + ci) * 3 + 1];
            const ull wv = c_params[WOFF + (co * CIN + ci) * 3 + 2];
#pragma unroll
            for (int k = 0; k < NPOUT; k++) {
                fma2(acc[co * NPOUT + k], w0, in[ci * NPIN + k]);
                fma2(acc[co * NPOUT + k], w1, o[k]);
                fma2(acc[co * NPOUT + k], wv, in[ci * NPIN + k + 1]);
            }
        }
    }

#pragma unroll
    for (int co = 0; co < FEAT; co++)
#pragma unroll
        for (int k = 0; k < NPOUT; k++) {
            float lo, hi;
            unpackf2(acc[co * NPOUT + k], lo, hi);
            out[co * NPOUT + k] = packf2(fmaxf(lo, 0.0f), fmaxf(hi, 0.0f));
        }
}

// ---------------------------------------------------------------------------
// Per-(node,lane) pass body, common to all pass kernel variants.
// ---------------------------------------------------------------------------
__device__ __forceinline__ void node_pass(int n, int lane,
                                          const float* __restrict__ zin,
                                          float* __restrict__ zout,
                                          const int* __restrict__ nbr) {
    // Gather 16 neighbor states (warp-uniform index row, coalesced state rows).
    ull gp[DEG / 2];
    const int4* nb4 = reinterpret_cast<const int4*>(nbr + n * DEG);
#pragma unroll
    for (int q = 0; q < 4; q++) {
        int4 v = __ldg(nb4 + q);
        float z0 = zin[v.x * BATCH + lane];
        float z1 = zin[v.y * BATCH + lane];
        float z2 = zin[v.z * BATCH + lane];
        float z3 = zin[v.w * BATCH + lane];
        gp[q * 2 + 0] = packf2(z0, z1);
        gp[q * 2 + 1] = packf2(z2, z3);
    }

    ull a[FEAT * 7];
    ull c[FEAT * 6];
    convp<1, 16,  OFF_WF,           OFF_BF          >(gp, a);  // a: 5 x w14
    convp<FEAT, 14, OFF_WM + 0*75, OFF_BM + 0*FEAT>(a, c);     // c: 5 x w12
    convp<FEAT, 12, OFF_WM + 1*75, OFF_BM + 1*FEAT>(c, a);     // a: 5 x w10
    convp<FEAT, 10, OFF_WM + 2*75, OFF_BM + 2*FEAT>(a, c);     // c: 5 x w8
    convp<FEAT, 8,  OFF_WM + 3*75, OFF_BM + 3*FEAT>(c, a);     // a: 5 x w6
    convp<FEAT, 6,  OFF_WM + 4*75, OFF_BM + 4*FEAT>(a, c);     // c: 5 x w4

    // Last conv: 5 -> 1, width 4 -> 2 packed {o0, o1}, then avgpool -> 1.
    ull accp = c_params[OFF_BL];
#pragma unroll
    for (int ci = 0; ci < FEAT; ci++) {
        ull p0 = c[ci * 2 + 0], p1 = c[ci * 2 + 1];
        float v0, v1, v2, v3;
        unpackf2(p0, v0, v1);
        unpackf2(p1, v2, v3);
        ull om = packf2(v1, v2);
        fma2(accp, c_params[OFF_WL + ci * 3 + 0], p0);
        fma2(accp, c_params[OFF_WL + ci * 3 + 1], om);
        fma2(accp, c_params[OFF_WL + ci * 3 + 2], p1);
    }
    float o0, o1;
    unpackf2(accp, o0, o1);
    o0 = fmaxf(o0, 0.0f);
    o1 = fmaxf(o1, 0.0f);

    zout[n * BATCH + lane] = 0.5f * (o0 + o1);
}

// ---------------------------------------------------------------------------
// Pass variants. Warp = one node across 32 batches (lane = batch).
// __launch_bounds__(128, 2): 256-reg cap guarantees a spill-free body.
// No smem staging, no __syncthreads: blocks start computing immediately.
// ---------------------------------------------------------------------------
__global__ __launch_bounds__(128, 2) void pass_full_kernel(int flip,
                                                           const int* __restrict__ nbr) {
    const float* zin  = flip ? g_zbuf1 : g_zbuf0;
    float*       zout = flip ? g_zbuf0 : g_zbuf1;
    int t = threadIdx.x;
    int n = (blockIdx.x * blockDim.x + t) >> 5;
    if (n >= N_NODES) return;
    node_pass(n, t & 31, zin, zout, nbr);
}

// Pass 3: only nodes in the frontier (neighbors of drivers). z0 -> z1.
__global__ __launch_bounds__(128, 2) void pass_frontier_kernel(const int* __restrict__ nbr) {
    int t = threadIdx.x;
    int w = (blockIdx.x * blockDim.x + t) >> 5;
    if (w >= g_fcount) return;
    node_pass(g_frontier[w], t & 31, g_zbuf0, g_zbuf1, nbr);
}

// Pass 4: only the driver nodes themselves. z1 -> z0.
__global__ __launch_bounds__(128, 2) void pass_driver_kernel(const int* __restrict__ nbr,
                                                             const int* __restrict__ drivers) {
    int t = threadIdx.x;
    int w = (blockIdx.x * blockDim.x + t) >> 5;
    if (w >= NDRV) return;
    node_pass(drivers[w], t & 31, g_zbuf1, g_zbuf0, nbr);
}

// ---------------------------------------------------------------------------
// Final softmax over [500 driver values union N-500 exact zeros]; output is
// nonzero only at driver columns (one-hot driver_matrix handled analytically):
//   denom = sum_drv exp(v-m) + (N-NDRV)*exp(-m),  m = max(0, max_drv v).
// One block per batch. Driver values live in g_zbuf0 after pass 4.
// ---------------------------------------------------------------------------
__global__ void softmax_kernel(const int* __restrict__ drivers,
                               float* __restrict__ out) {
    const float* __restrict__ zt = g_zbuf0;
    int b = blockIdx.x;
    int t = threadIdx.x;
    __shared__ float sred[256];

    float lm = 0.0f;  // implicit zeros of the non-driver entries
    for (int j = t; j < NDRV; j += 256)
        lm = fmaxf(lm, zt[drivers[j] * BATCH + b]);
    sred[t] = lm;
    __syncthreads();
    for (int s = 128; s > 0; s >>= 1) {
        if (t < s) sred[t] = fmaxf(sred[t], sred[t + s]);
        __syncthreads();
    }
    float m = sred[0];
    __syncthreads();

    float ls = 0.0f;
    for (int j = t; j < NDRV; j += 256)
        ls += expf(zt[drivers[j] * BATCH + b] - m);
    sred[t] = ls;
    __syncthreads();
    for (int s = 128; s > 0; s >>= 1) {
        if (t < s) sred[t] += sred[t + s];
        __syncthreads();
    }
    float denom = sred[0] + (float)(N_NODES - NDRV) * expf(-m);
    float inv = 1.0f / denom;

    for (int j = t; j < NDRV; j += 256) {
        int n = drivers[j];
        out[b * N_NODES + n] = expf(zt[n * BATCH + b] - m) * inv;
    }
}

// ---------------------------------------------------------------------------
extern "C" void kernel_launch(void* const* d_in, const int* in_sizes, int n_in,
                              void* d_out, int out_size) {
    const float* x       = (const float*)d_in[0];
    const int*   nbr     = (const int*)  d_in[1];
    const int*   drivers = (const int*)  d_in[2];
    // d_in[3] = driver_matrix (one-hot; handled analytically)
    const float* wf = (const float*)d_in[4];
    const float* bf = (const float*)d_in[5];
    const float* wm = (const float*)d_in[6];
    const float* bm = (const float*)d_in[7];
    const float* wl = (const float*)d_in[8];
    const float* bl = (const float*)d_in[9];
    float* out = (float*)d_out;

    const int FULL_BLOCKS = (N_NODES * 32 + 127) / 128;      // one warp per node
    const int FRONT_BLOCKS = (FMAX * 32 + 127) / 128;        // worst-case frontier
    const int DRV_BLOCKS = (NDRV * 32 + 127) / 128;

    // 0: pack duplicated params into staging global.
    pack_params<<<2, 256>>>(wf, bf, wm, bm, wl, bl);

    // Copy staging -> __constant__ (device-to-device, graph-capturable).
    void* src = nullptr;
    cudaGetSymbolAddress(&src, g_params);
    cudaMemcpyToSymbolAsync(c_params, src, NPARAM * sizeof(ull), 0,
                            cudaMemcpyDeviceToDevice, 0);

    // 1 (or 2): transpose + output-zero + mark-clear, fused.
    {
        dim3 tb(32, 8);
        transpose_prep_kernel<<<(N_NODES + 31) / 32, tb>>>(x, (float4*)out);
    }

    // pass_full sits at kernel index 2&3 (memcpy not counted) or 3&4
    // (memcpy counted) -> ncu's fixed slot 3 lands on pass_full either way.
    pass_full_kernel<<<FULL_BLOCKS, 128>>>(0, nbr);          // z0 -> z1 (all)
    pass_full_kernel<<<FULL_BLOCKS, 128>>>(1, nbr);          // z1 -> z0 (all)
    build_frontier_kernel<<<(NDRV * DEG + 255) / 256, 256>>>(drivers, nbr);
    pass_frontier_kernel<<<FRONT_BLOCKS, 128>>>(nbr);        // z0 -> z1 (frontier)
    pass_driver_kernel<<<DRV_BLOCKS, 128>>>(nbr, drivers);   // z1 -> z0 (drivers)
    softmax_kernel<<<BATCH, 256>>>(drivers, out);
}